// round 1
// baseline (speedup 1.0000x reference)
#include <cuda_runtime.h>
#include <cuda_bf16.h>
#include <math.h>

#define N        4096
#define T        4096
#define WASH     200
#define NBLK     128
#define TPB      256
#define RPC      (N / NBLK)          // 32 rows per CTA
#define RPW      (RPC / 8)           // 4 rows per warp
#define SEG_CAP  27648               // per-CTA nnz capacity (mean ~26214, +~10 sigma)
#define NNZ_CAP  3500000             // global nnz capacity (mean ~3.36M)

// ---------------- device globals (no allocations allowed) ----------------
__device__ int            g_row_nnz[N];
__device__ int            g_row_ptr[N + 1];
__device__ float          g_val[NNZ_CAP];
__device__ unsigned short g_col[NNZ_CAP];
__device__ float          g_x[2][N];
__device__ float          g_wv[N];       // wv[mask[i]] = w_out[i]
__device__ unsigned       g_bar;         // monotonic barrier counter (reset each launch)

// ---------------- prep: count nonzeros per row (1 warp per row) ----------
__global__ void k_count(const float* __restrict__ w) {
    int wid  = blockIdx.x * (TPB / 32) + (threadIdx.x >> 5);
    int lane = threadIdx.x & 31;
    if (wid >= N) return;
    const float* row = w + (size_t)wid * N;
    int cnt = 0;
    for (int j = lane; j < N; j += 32) cnt += (row[j] != 0.0f);
    for (int o = 16; o; o >>= 1) cnt += __shfl_xor_sync(~0u, cnt, o);
    if (lane == 0) g_row_nnz[wid] = cnt;
}

// ---------------- prep: exclusive prefix scan of row_nnz (1 block) -------
__global__ void k_scan() {
    __shared__ int sc[1024];
    int i = threadIdx.x;
    int a0 = g_row_nnz[4 * i + 0];
    int a1 = g_row_nnz[4 * i + 1];
    int a2 = g_row_nnz[4 * i + 2];
    int a3 = g_row_nnz[4 * i + 3];
    int s  = a0 + a1 + a2 + a3;
    sc[i] = s;
    __syncthreads();
    for (int d = 1; d < 1024; d <<= 1) {
        int v   = sc[i];
        int add = (i >= d) ? sc[i - d] : 0;
        __syncthreads();
        sc[i] = v + add;
        __syncthreads();
    }
    int excl = sc[i] - s;
    g_row_ptr[4 * i + 0] = excl;
    g_row_ptr[4 * i + 1] = excl + a0;
    g_row_ptr[4 * i + 2] = excl + a0 + a1;
    g_row_ptr[4 * i + 3] = excl + a0 + a1 + a2;
    if (i == 1023) g_row_ptr[N] = sc[1023];
}

// ---------------- prep: compact rows into CSR (1 warp per row) -----------
__global__ void k_fill(const float* __restrict__ w) {
    int wid  = blockIdx.x * (TPB / 32) + (threadIdx.x >> 5);
    int lane = threadIdx.x & 31;
    if (wid >= N) return;
    const float* row = w + (size_t)wid * N;
    int base = g_row_ptr[wid];
    for (int c = 0; c < N; c += 32) {
        float v = row[c + lane];
        unsigned m = __ballot_sync(~0u, v != 0.0f);
        if (v != 0.0f) {
            int pos = base + __popc(m & ((1u << lane) - 1u));
            g_val[pos] = v;
            g_col[pos] = (unsigned short)(c + lane);
        }
        base += __popc(m);
    }
}

// ---------------- prep: wv scatter, zero output, reset barrier -----------
__global__ void k_prep(const float* __restrict__ w_out,
                       const int* __restrict__ mask,
                       float* __restrict__ out, int out_n) {
    int i = blockIdx.x * blockDim.x + threadIdx.x;
    if (i < N)     g_wv[mask[i]] = w_out[i];
    if (i < out_n) out[i] = 0.0f;
    if (i == 0)    g_bar = 0u;
}

// ---------------- main persistent ESN kernel -----------------------------
__global__ void __launch_bounds__(TPB, 1)
k_esn(const float* __restrict__ u, const float* __restrict__ w_in,
      float* __restrict__ out) {
    extern __shared__ unsigned char smem_raw[];
    float*          sval = (float*)smem_raw;                         // SEG_CAP
    unsigned short* scol = (unsigned short*)(sval + SEG_CAP);        // SEG_CAP
    float*          sx   = (float*)(scol + SEG_CAP);                 // N
    int*            lrp  = (int*)(sx + N);                           // RPC+1
    float*          wsum = (float*)(lrp + RPC + 1);                  // 8

    const int c    = blockIdx.x;
    const int tid  = threadIdx.x;
    const int wid  = tid >> 5;
    const int lane = tid & 31;
    const int row0 = c * RPC;

    const int seg_beg = g_row_ptr[row0];
    int seg_len = g_row_ptr[row0 + RPC] - seg_beg;
    if (seg_len > SEG_CAP) seg_len = SEG_CAP;   // statistically unreachable

    for (int r = tid; r <= RPC; r += TPB) lrp[r] = g_row_ptr[row0 + r] - seg_beg;
    for (int k = tid; k < seg_len; k += TPB) {
        sval[k] = g_val[seg_beg + k];
        scol[k] = g_col[seg_beg + k];
    }
    for (int j = tid; j < N; j += TPB) sx[j] = 0.0f;
    __syncthreads();

    // hoist per-warp row metadata into registers
    int   kb[RPW], ke[RPW];
    float winr[RPW], wvr[RPW];
    #pragma unroll
    for (int rr = 0; rr < RPW; rr++) {
        int lr = wid * RPW + rr;
        kb[rr] = lrp[lr];
        ke[rr] = lrp[lr + 1];
        int gr = row0 + lr;
        winr[rr] = w_in[gr];
        wvr[rr]  = g_wv[gr];
    }

    for (int t = 0; t < T; ++t) {
        const float ut = __ldg(&u[t]);
        float* xout = g_x[t & 1];
        float partial = 0.0f;
        #pragma unroll
        for (int rr = 0; rr < RPW; rr++) {
            float s = 0.0f;
            #pragma unroll 4
            for (int k = kb[rr] + lane; k < ke[rr]; k += 32)
                s += sval[k] * sx[scol[k]];
            for (int o = 16; o; o >>= 1) s += __shfl_xor_sync(~0u, s, o);
            if (lane == 0) {
                float xv = tanhf(winr[rr] * ut + s);
                int gr = row0 + wid * RPW + rr;
                __stcg(&xout[gr], xv);
                partial += wvr[rr] * xv;
            }
        }
        if (lane == 0) wsum[wid] = partial;
        __threadfence();
        __syncthreads();

        if (tid == 0) {
            if (t >= WASH) {
                float ys = 0.0f;
                #pragma unroll
                for (int w = 0; w < 8; w++) ys += wsum[w];
                atomicAdd(&out[t - WASH], ys);   // off-critical-path RED
            }
            unsigned target = (unsigned)(t + 1) * NBLK;
            atomicAdd(&g_bar, 1u);
            while (*(volatile unsigned*)&g_bar < target) { }
        }
        __syncthreads();

        if (t + 1 < T) {
            const float* xs = xout;
            for (int j = tid; j < N; j += TPB) sx[j] = __ldcg(&xs[j]);
        }
    }
}

// ---------------- launch ---------------------------------------------------
extern "C" void kernel_launch(void* const* d_in, const int* in_sizes, int n_in,
                              void* d_out, int out_size) {
    const float* u     = (const float*)d_in[0];
    const float* w_res = (const float*)d_in[1];
    const float* w_in  = (const float*)d_in[2];
    const float* w_out = (const float*)d_in[3];
    const int*   mask  = (const int*)d_in[4];
    float*       out   = (float*)d_out;

    const int smem_main = SEG_CAP * 4 + SEG_CAP * 2 + N * 4 + (RPC + 1) * 4 + 8 * 4;
    cudaFuncSetAttribute(k_esn, cudaFuncAttributeMaxDynamicSharedMemorySize, smem_main);

    const int warps_grid = (N * 32 + TPB - 1) / TPB;   // 1 warp per row -> 512 blocks
    k_count<<<warps_grid, TPB>>>(w_res);
    k_scan<<<1, 1024>>>();
    k_fill<<<warps_grid, TPB>>>(w_res);
    k_prep<<<(N + TPB - 1) / TPB, TPB>>>(w_out, mask, out, out_size);
    k_esn<<<NBLK, TPB, smem_main>>>(u, w_in, out);
}

// round 2
// speedup vs baseline: 1.2828x; 1.2828x over previous
#include <cuda_runtime.h>
#include <cuda_bf16.h>
#include <math.h>

#define N        4096
#define T        4096
#define WASH     200
#define NBLK     128
#define TPB      256
#define RPC      (N / NBLK)          // 32 rows per CTA
#define RPW      (RPC / 8)           // 4 rows per warp
#define L_CAP    1472                // per-CTA per-lane ELL word capacity (mean ~1236, +20sd)
#define ELL_CAP  6291456             // global ELL words (mean ~5.06M)

// ---------------- device globals (no allocations allowed) ----------------
__device__ int      g_wpad[N];        // per-row padded (mult of 4) per-lane width
__device__ int      g_off[N + 1];     // exclusive prefix of g_wpad (per-lane units)
__device__ unsigned g_ell[ELL_CAP];   // packed (val & ~127) | j  words, interleaved-4 layout
__device__ float    g_x[2][N];
__device__ float    g_wv[N];          // wv[mask[i]] = w_out[i]
__device__ unsigned g_bar;            // monotonic barrier counter (reset each launch)

// ---- prep 1: per-row, per-bank widths (1 warp per row) -------------------
// lane l counts nonzeros at columns col = 32k + l  (k in [0,128))
__global__ void k_width(const float* __restrict__ w) {
    int r    = blockIdx.x * (TPB / 32) + (threadIdx.x >> 5);
    int lane = threadIdx.x & 31;
    if (r >= N) return;
    const float* row = w + (size_t)r * N;
    int cnt = 0;
    #pragma unroll 8
    for (int k = 0; k < N / 32; k++) cnt += (row[k * 32 + lane] != 0.0f);
    for (int o = 16; o; o >>= 1) {
        int v = __shfl_xor_sync(~0u, cnt, o);
        cnt = v > cnt ? v : cnt;
    }
    if (lane == 0) g_wpad[r] = (cnt + 3) & ~3;   // pad to multiple of 4
}

// ---- prep 2: exclusive prefix scan of g_wpad (1 block) -------------------
__global__ void k_scan() {
    __shared__ int sc[1024];
    int i = threadIdx.x;
    int a0 = g_wpad[4 * i + 0];
    int a1 = g_wpad[4 * i + 1];
    int a2 = g_wpad[4 * i + 2];
    int a3 = g_wpad[4 * i + 3];
    int s  = a0 + a1 + a2 + a3;
    sc[i] = s;
    __syncthreads();
    for (int d = 1; d < 1024; d <<= 1) {
        int v   = sc[i];
        int add = (i >= d) ? sc[i - d] : 0;
        __syncthreads();
        sc[i] = v + add;
        __syncthreads();
    }
    int excl = sc[i] - s;
    g_off[4 * i + 0] = excl;
    g_off[4 * i + 1] = excl + a0;
    g_off[4 * i + 2] = excl + a0 + a1;
    g_off[4 * i + 3] = excl + a0 + a1 + a2;
    if (i == 1023) g_off[N] = sc[1023];
}

// ---- prep 3: fill bank-sliced ELL with packed words (1 warp per row) -----
// Storage layout (interleaved-4, per-lane units): element (i, lane) of a row
// with base b lives at word  b*32 + (i>>2)*128 + lane*4 + (i&3).
// Packed word = (round_to_7(bits(val))) | j, where col = 32*j + lane.
__global__ void k_fillell(const float* __restrict__ w) {
    int r    = blockIdx.x * (TPB / 32) + (threadIdx.x >> 5);
    int lane = threadIdx.x & 31;
    if (r >= N) return;
    const float* row = w + (size_t)r * N;
    int b   = g_off[r];
    int wid = g_off[r + 1] - b;
    unsigned* base = g_ell + (size_t)b * 32;
    int i = 0;
    for (int k = 0; k < N / 32; k++) {
        float v = row[k * 32 + lane];
        if (v != 0.0f) {
            unsigned bits = (__float_as_uint(v) + 64u) & ~127u;   // round low 7 bits away
            base[(i >> 2) * 128 + lane * 4 + (i & 3)] = bits | (unsigned)k;
            i++;
        }
    }
    for (; i < wid; i++)
        base[(i >> 2) * 128 + lane * 4 + (i & 3)] = 0u;           // padding: 0*sx[lane]
}

// ---- prep 4: wv scatter, zero output, reset barrier, zero x0 -------------
__global__ void k_prep(const float* __restrict__ w_out,
                       const int* __restrict__ mask,
                       float* __restrict__ out, int out_n) {
    int i = blockIdx.x * blockDim.x + threadIdx.x;
    if (i < N)     g_wv[mask[i]] = w_out[i];
    if (i < out_n) out[i] = 0.0f;
    if (i == 0)    g_bar = 0u;
}

// ---------------- main persistent ESN kernel -----------------------------
__global__ void __launch_bounds__(TPB, 1)
k_esn(const float* __restrict__ u, const float* __restrict__ w_in,
      float* __restrict__ out) {
    extern __shared__ unsigned char smem_raw[];
    unsigned* sell = (unsigned*)smem_raw;                 // L_CAP*32 words
    float*    sx   = (float*)(sell + L_CAP * 32);         // N
    int*      lrp  = (int*)(sx + N);                      // RPC+1 (per-lane units)
    float*    wsum = (float*)(lrp + RPC + 1);             // 8

    const int c    = blockIdx.x;
    const int tid  = threadIdx.x;
    const int wid  = tid >> 5;
    const int lane = tid & 31;
    const int row0 = c * RPC;

    const int seg_beg = g_off[row0];
    int seg_pl = g_off[row0 + RPC] - seg_beg;             // per-lane words
    if (seg_pl > L_CAP) seg_pl = L_CAP;                   // statistically unreachable

    for (int r = tid; r <= RPC; r += TPB) {
        int v = g_off[row0 + r] - seg_beg;
        lrp[r] = v > L_CAP ? L_CAP : v;
    }
    {   // copy ELL segment (16B-aligned, offsets are multiples of 4 per-lane units)
        const uint4* src = (const uint4*)(g_ell + (size_t)seg_beg * 32);
        uint4*       dst = (uint4*)sell;
        int nvec = seg_pl * 8;                            // seg_pl*32/4
        for (int k = tid; k < nvec; k += TPB) dst[k] = src[k];
    }
    for (int j = tid; j < N; j += TPB) sx[j] = 0.0f;
    __syncthreads();

    // hoist per-warp row metadata into registers
    int   kb[RPW], kw[RPW];
    float winr[RPW], wvr[RPW];
    #pragma unroll
    for (int rr = 0; rr < RPW; rr++) {
        int lr = wid * RPW + rr;
        kb[rr] = lrp[lr];
        kw[rr] = lrp[lr + 1] - lrp[lr];
        int gr = row0 + lr;
        winr[rr] = w_in[gr];
        wvr[rr]  = g_wv[gr];
    }

    for (int t = 0; t < T; ++t) {
        const float ut = __ldg(&u[t]);
        float* xout = g_x[t & 1];
        float partial = 0.0f;
        #pragma unroll
        for (int rr = 0; rr < RPW; rr++) {
            const uint4* p = (const uint4*)(sell + kb[rr] * 32 + lane * 4);
            float s = 0.0f;
            for (int i = 0; i < kw[rr]; i += 4, p += 32) {
                uint4 q = *p;
                s += __uint_as_float(q.x & 0xFFFFFF80u) * sx[((q.x & 127u) << 5) + lane];
                s += __uint_as_float(q.y & 0xFFFFFF80u) * sx[((q.y & 127u) << 5) + lane];
                s += __uint_as_float(q.z & 0xFFFFFF80u) * sx[((q.z & 127u) << 5) + lane];
                s += __uint_as_float(q.w & 0xFFFFFF80u) * sx[((q.w & 127u) << 5) + lane];
            }
            for (int o = 16; o; o >>= 1) s += __shfl_xor_sync(~0u, s, o);
            if (lane == 0) {
                float xv = tanhf(winr[rr] * ut + s);
                int gr = row0 + wid * RPW + rr;
                __stcg(&xout[gr], xv);
                partial += wvr[rr] * xv;
            }
        }
        if (lane == 0) wsum[wid] = partial;
        __syncthreads();   // orders the stcg x-writes before tid0's release below

        if (tid == 0) {
            // release-arrive publishes this CTA's x writes (cumulative release)
            asm volatile("red.release.gpu.global.add.u32 [%0], %1;"
                         :: "l"(&g_bar), "r"(1u) : "memory");
            if (t >= WASH) {          // off-critical-path, overlaps propagation
                float ys = 0.0f;
                #pragma unroll
                for (int w = 0; w < 8; w++) ys += wsum[w];
                atomicAdd(&out[t - WASH], ys);
            }
            unsigned target = (unsigned)(t + 1) * NBLK;
            unsigned v;
            do {
                asm volatile("ld.acquire.gpu.global.u32 %0, [%1];"
                             : "=r"(v) : "l"(&g_bar) : "memory");
            } while (v < target);
        }
        __syncthreads();

        if (t + 1 < T) {
            const float4* xs4 = (const float4*)xout;
            float4*       sx4 = (float4*)sx;
            #pragma unroll
            for (int j = 0; j < 4; j++) {
                int idx = tid + j * TPB;                 // 1024 float4s total
                sx4[idx] = __ldcg(&xs4[idx]);
            }
        }
    }
}

// ---------------- launch ---------------------------------------------------
extern "C" void kernel_launch(void* const* d_in, const int* in_sizes, int n_in,
                              void* d_out, int out_size) {
    const float* u     = (const float*)d_in[0];
    const float* w_res = (const float*)d_in[1];
    const float* w_in  = (const float*)d_in[2];
    const float* w_out = (const float*)d_in[3];
    const int*   mask  = (const int*)d_in[4];
    float*       out   = (float*)d_out;

    const int smem_main = L_CAP * 32 * 4 + N * 4 + (RPC + 1) * 4 + 8 * 4;
    cudaFuncSetAttribute(k_esn, cudaFuncAttributeMaxDynamicSharedMemorySize, smem_main);

    const int rows_grid = (N * 32 + TPB - 1) / TPB;   // 1 warp per row -> 512 blocks
    k_width<<<rows_grid, TPB>>>(w_res);
    k_scan<<<1, 1024>>>();
    k_fillell<<<rows_grid, TPB>>>(w_res);
    k_prep<<<(N + TPB - 1) / TPB, TPB>>>(w_out, mask, out, out_size);
    k_esn<<<NBLK, TPB, smem_main>>>(u, w_in, out);
}